// round 2
// baseline (speedup 1.0000x reference)
#include <cuda_runtime.h>
#include <cuda_bf16.h>
#include <math.h>
#include <stdint.h>

#define N_NODES_C 100000
#define N_EDGES_C 1000000
#define DIM 64          // NODE_DIM
#define EDIM 32         // EDGE_DIM
#define NGAUSS 16
#define HID 128
#define NLAYERS 4
#define CATD 160        // 2*DIM + EDIM
#define NGRAPHS 64

#define TILE_E 64
#define XP 164          // padded X row pitch (floats)
#define HP 132          // padded H row pitch (floats)
#define LYR_THREADS 128
#define LYR_GRID 148

// ---- scratch (static device globals; no allocation allowed) ----
__device__ __align__(256) float g_h[N_NODES_C * DIM];
__device__ __align__(256) float g_agg[N_NODES_C * DIM];
__device__ __align__(256) float g_ea[(size_t)N_EDGES_C * EDIM];
__device__ __align__(256) float g_pool[NGRAPHS * DIM];
__device__ __align__(256) float g_cnt[NGRAPHS];

// shared bytes for layer kernel:
// W1 160*128 + W2 128*64 + b1 128 + b2 64 + X 64*164 + H 64*132 (floats) + 64 ints
#define SMEM_FLOATS (CATD*HID + HID*DIM + HID + DIM + TILE_E*XP + TILE_E*HP)
#define SMEM_BYTES  (SMEM_FLOATS*4 + TILE_E*4)

__device__ __forceinline__ void red_add_v4(float* p, float x, float y, float z, float w) {
    asm volatile("red.global.add.v4.f32 [%0], {%1,%2,%3,%4};"
                 :: "l"(p), "f"(x), "f"(y), "f"(z), "f"(w) : "memory");
}

// ---------------- init: h = embed[atoms], agg = 0 ----------------
__global__ void k_init_nodes(const int* __restrict__ atoms, const float* __restrict__ emb) {
    int i = blockIdx.x * blockDim.x + threadIdx.x;
    if (i < N_NODES_C * DIM) {
        int n = i >> 6, d = i & 63;
        g_h[i] = emb[atoms[n] * DIM + d];
        g_agg[i] = 0.0f;
    }
}

__global__ void k_zero_pool() {
    int i = blockIdx.x * blockDim.x + threadIdx.x;
    if (i < NGRAPHS * DIM) g_pool[i] = 0.0f;
    if (i < NGRAPHS) g_cnt[i] = 0.0f;
}

// ---------------- edge attributes: RBF(dist) ++ subunit embed ----------------
__global__ void k_edge_attr(const int* __restrict__ ei,
                            const float* __restrict__ coords,
                            const int* __restrict__ isrec,
                            const float* __restrict__ sub) {
    int e = blockIdx.x * blockDim.x + threadIdx.x;
    if (e >= N_EDGES_C) return;
    int s = ei[e];
    int t = ei[N_EDGES_C + e];
    float dx = coords[s*3+0] - coords[t*3+0];
    float dy = coords[s*3+1] - coords[t*3+1];
    float dz = coords[s*3+2] - coords[t*3+2];
    float dist = sqrtf(dx*dx + dy*dy + dz*dz);
    const float coeff = -4.5f;  // -0.5 / (5/15)^2
    float* row = g_ea + (size_t)e * EDIM;
    #pragma unroll
    for (int g = 0; g < NGAUSS; g++) {
        float off = 5.0f * (float)g * (1.0f / 15.0f);
        float d0 = dist - off;
        row[g] = __expf(coeff * d0 * d0);
    }
    int kind = (isrec[s] != isrec[t]) ? 1 : 0;
    #pragma unroll
    for (int g = 0; g < NGAUSS; g++) row[NGAUSS + g] = sub[kind * NGAUSS + g];
}

// ---------------- fused per-layer edge MLP + scatter-add ----------------
extern __shared__ float smem[];

__global__ __launch_bounds__(LYR_THREADS, 1)
void k_layer(const int* __restrict__ ei,
             const float* __restrict__ W1, const float* __restrict__ b1,
             const float* __restrict__ W2, const float* __restrict__ b2) {
    float* sW1 = smem;                        // [160][128]
    float* sW2 = sW1 + CATD * HID;            // [128][64]
    float* sB1 = sW2 + HID * DIM;             // [128]
    float* sB2 = sB1 + HID;                   // [64]
    float* sX  = sB2 + DIM;                   // [64][XP]
    float* sH  = sX + TILE_E * XP;            // [64][HP]
    int*  sDst = (int*)(sH + TILE_E * HP);    // [64]

    const int tid = threadIdx.x;

    for (int i = tid; i < CATD * HID; i += LYR_THREADS) sW1[i] = W1[i];
    for (int i = tid; i < HID * DIM; i += LYR_THREADS)  sW2[i] = W2[i];
    if (tid < HID) sB1[tid] = b1[tid];
    if (tid < DIM) sB2[tid] = b2[tid];
    __syncthreads();

    const int* src = ei;
    const int* dst = ei + N_EDGES_C;
    const int tx = tid & 15;   // 16 col groups
    const int ty = tid >> 4;   // 8 row groups
    const int NT = N_EDGES_C / TILE_E;

    for (int tile = blockIdx.x; tile < NT; tile += gridDim.x) {
        const int e0 = tile * TILE_E;

        // ---- gather X rows: [h[dst] | h[src] | edge_attr], float4 granularity
        for (int t = tid; t < TILE_E * 40; t += LYR_THREADS) {
            int e = t / 40, q = t - e * 40;
            int ge = e0 + e;
            const float4* p;
            if (q < 16)        p = (const float4*)(g_h  + (size_t)dst[ge] * DIM) + q;
            else if (q < 32)   p = (const float4*)(g_h  + (size_t)src[ge] * DIM) + (q - 16);
            else               p = (const float4*)(g_ea + (size_t)ge * EDIM) + (q - 32);
            *(float4*)&sX[e * XP + q * 4] = *p;
        }
        if (tid < TILE_E) sDst[tid] = dst[e0 + tid];
        __syncthreads();

        // ---- GEMM1: [64,160] x [160,128] with 8x8 register tile, then silu -> sH
        float acc[8][8];
        #pragma unroll
        for (int i = 0; i < 8; i++)
            #pragma unroll
            for (int j = 0; j < 8; j++) acc[i][j] = 0.0f;

        #pragma unroll 2
        for (int k = 0; k < CATD; k++) {
            float a[8];
            #pragma unroll
            for (int i = 0; i < 8; i++) a[i] = sX[(ty * 8 + i) * XP + k];
            float4 wA = *(float4*)&sW1[k * HID + tx * 8];
            float4 wB = *(float4*)&sW1[k * HID + tx * 8 + 4];
            float w[8] = {wA.x, wA.y, wA.z, wA.w, wB.x, wB.y, wB.z, wB.w};
            #pragma unroll
            for (int i = 0; i < 8; i++)
                #pragma unroll
                for (int j = 0; j < 8; j++) acc[i][j] += a[i] * w[j];
        }
        #pragma unroll
        for (int i = 0; i < 8; i++) {
            #pragma unroll
            for (int j = 0; j < 8; j++) {
                float v = acc[i][j] + sB1[tx * 8 + j];
                v = v / (1.0f + __expf(-v));          // silu
                sH[(ty * 8 + i) * HP + tx * 8 + j] = v;
            }
        }
        __syncthreads();

        // ---- GEMM2: [64,128] x [128,64] with 8x4 register tile
        float acc2[8][4];
        #pragma unroll
        for (int i = 0; i < 8; i++)
            #pragma unroll
            for (int j = 0; j < 4; j++) acc2[i][j] = 0.0f;

        #pragma unroll 2
        for (int k = 0; k < HID; k++) {
            float a[8];
            #pragma unroll
            for (int i = 0; i < 8; i++) a[i] = sH[(ty * 8 + i) * HP + k];
            float4 w = *(float4*)&sW2[k * DIM + tx * 4];
            #pragma unroll
            for (int i = 0; i < 8; i++) {
                acc2[i][0] += a[i] * w.x;
                acc2[i][1] += a[i] * w.y;
                acc2[i][2] += a[i] * w.z;
                acc2[i][3] += a[i] * w.w;
            }
        }
        float bx = sB2[tx * 4], by = sB2[tx * 4 + 1], bz = sB2[tx * 4 + 2], bw = sB2[tx * 4 + 3];
        #pragma unroll
        for (int i = 0; i < 8; i++) {
            int e = ty * 8 + i;
            float* p = g_agg + (size_t)sDst[e] * DIM + tx * 4;
            red_add_v4(p, acc2[i][0] + bx, acc2[i][1] + by, acc2[i][2] + bz, acc2[i][3] + bw);
        }
        __syncthreads();
    }
}

// ---------------- h = relu(h + agg); agg = 0 ----------------
__global__ void k_update() {
    int i = blockIdx.x * blockDim.x + threadIdx.x;
    if (i < N_NODES_C * DIM) {
        float v = g_h[i] + g_agg[i];
        g_h[i] = v > 0.0f ? v : 0.0f;
        g_agg[i] = 0.0f;
    }
}

// ---------------- pooling (segment sums + counts) ----------------
__global__ void k_pool(const int* __restrict__ batch) {
    int n = blockIdx.x * blockDim.x + threadIdx.x;
    if (n >= N_NODES_C) return;
    int b = batch[n];
    const float4* hp = (const float4*)(g_h + (size_t)n * DIM);
    float* pp = g_pool + b * DIM;
    #pragma unroll
    for (int q = 0; q < 16; q++) {
        float4 v = hp[q];
        red_add_v4(pp + q * 4, v.x, v.y, v.z, v.w);
    }
    atomicAdd(&g_cnt[b], 1.0f);
}

// ---------------- final FC ----------------
__global__ void k_final(const float* __restrict__ fcw, const float* __restrict__ fcb,
                        float* __restrict__ out) {
    int g = threadIdx.x;
    if (g < NGRAPHS) {
        float c = fmaxf(g_cnt[g], 1.0f);
        float inv = 1.0f / c;
        float s = 0.0f;
        #pragma unroll
        for (int d = 0; d < DIM; d++) s += (g_pool[g * DIM + d] * inv) * fcw[d];
        out[g] = s + fcb[0];
    }
}

extern "C" void kernel_launch(void* const* d_in, const int* in_sizes, int n_in,
                              void* d_out, int out_size) {
    const int*   atoms  = (const int*)d_in[0];
    const int*   ei     = (const int*)d_in[1];   // [2, E]: src row then dst row
    const float* coords = (const float*)d_in[2];
    const int*   isrec  = (const int*)d_in[3];
    const int*   batch  = (const int*)d_in[4];
    const float* emb    = (const float*)d_in[5];
    const float* sub    = (const float*)d_in[6];
    const float* W1     = (const float*)d_in[7]; // [4,160,128]
    const float* b1     = (const float*)d_in[8]; // [4,128]
    const float* W2     = (const float*)d_in[9]; // [4,128,64]
    const float* b2     = (const float*)d_in[10];// [4,64]
    const float* fcw    = (const float*)d_in[11];// [64,1]
    const float* fcb    = (const float*)d_in[12];// [1]
    float* out = (float*)d_out;

    cudaFuncSetAttribute(k_layer, cudaFuncAttributeMaxDynamicSharedMemorySize, SMEM_BYTES);

    k_init_nodes<<<(N_NODES_C * DIM + 255) / 256, 256>>>(atoms, emb);
    k_zero_pool<<<16, 256>>>();
    k_edge_attr<<<(N_EDGES_C + 255) / 256, 256>>>(ei, coords, isrec, sub);

    for (int l = 0; l < NLAYERS; l++) {
        k_layer<<<LYR_GRID, LYR_THREADS, SMEM_BYTES>>>(
            ei, W1 + (size_t)l * CATD * HID, b1 + (size_t)l * HID,
            W2 + (size_t)l * HID * DIM, b2 + (size_t)l * DIM);
        k_update<<<(N_NODES_C * DIM + 255) / 256, 256>>>();
    }

    k_pool<<<(N_NODES_C + 255) / 256, 256>>>(batch);
    k_final<<<1, 64>>>(fcw, fcb, out);
}

// round 4
// speedup vs baseline: 2.0445x; 2.0445x over previous
#include <cuda_runtime.h>
#include <cuda_bf16.h>
#include <math.h>
#include <stdint.h>

#define N_NODES_C 100000
#define N_EDGES_C 1000000
#define DIM 64          // NODE_DIM
#define EDIM 32         // EDGE_DIM
#define NGAUSS 16
#define HID 128
#define NLAYERS 4
#define CATD 160        // 2*DIM + EDIM
#define NGRAPHS 64

#define TILE_E 64
#define XP 164          // padded X row pitch (floats)
#define HP 132          // padded H row pitch (floats)
#define LYR_THREADS 256
#define LYR_GRID 148

// ---- scratch (static device globals; no allocation allowed) ----
__device__ __align__(256) float g_h[N_NODES_C * DIM];
__device__ __align__(256) float g_agg[N_NODES_C * DIM];
__device__ __align__(256) float g_ea[(size_t)N_EDGES_C * EDIM];
__device__ __align__(256) float g_pool[NGRAPHS * DIM];
__device__ __align__(256) float g_cnt[NGRAPHS];

// shared floats: W1 160*128 + W2 128*64 + b1 128 + b2 64 + X 64*164 + H 64*132 + dst ints
#define SMEM_FLOATS (CATD*HID + HID*DIM + HID + DIM + TILE_E*XP + TILE_E*HP)
#define SMEM_BYTES  (SMEM_FLOATS*4 + TILE_E*4)

// ---- packed f32x2 helpers (sm_103a) ----
#define FFMA2(acc, a, b) \
    asm volatile("fma.rn.f32x2 %0, %1, %2, %0;" : "+l"(acc) : "l"(a), "l"(b))
#define PACK2(out, lo, hi) \
    asm("mov.b64 %0, {%1, %2};" : "=l"(out) : "r"(__float_as_uint(lo)), "r"(__float_as_uint(hi)))
#define UNPACK2(lo, hi, in) do { unsigned _ulo, _uhi; \
    asm("mov.b64 {%0, %1}, %2;" : "=r"(_ulo), "=r"(_uhi) : "l"(in)); \
    lo = __uint_as_float(_ulo); hi = __uint_as_float(_uhi); } while (0)

__device__ __forceinline__ void red_add_v4(float* p, float x, float y, float z, float w) {
    asm volatile("red.global.add.v4.f32 [%0], {%1,%2,%3,%4};"
                 :: "l"(p), "f"(x), "f"(y), "f"(z), "f"(w) : "memory");
}

// ---------------- init: h = embed[atoms], agg = 0 ----------------
__global__ void k_init_nodes(const int* __restrict__ atoms, const float* __restrict__ emb) {
    int i = blockIdx.x * blockDim.x + threadIdx.x;
    if (i < N_NODES_C * DIM) {
        int n = i >> 6, d = i & 63;
        g_h[i] = emb[atoms[n] * DIM + d];
        g_agg[i] = 0.0f;
    }
}

__global__ void k_zero_pool() {
    int i = blockIdx.x * blockDim.x + threadIdx.x;
    if (i < NGRAPHS * DIM) g_pool[i] = 0.0f;
    if (i < NGRAPHS) g_cnt[i] = 0.0f;
}

// ---------------- edge attributes: RBF(dist) ++ subunit embed ----------------
__global__ void k_edge_attr(const int* __restrict__ ei,
                            const float* __restrict__ coords,
                            const int* __restrict__ isrec,
                            const float* __restrict__ sub) {
    int e = blockIdx.x * blockDim.x + threadIdx.x;
    if (e >= N_EDGES_C) return;
    int s = ei[e];
    int t = ei[N_EDGES_C + e];
    float dx = coords[s*3+0] - coords[t*3+0];
    float dy = coords[s*3+1] - coords[t*3+1];
    float dz = coords[s*3+2] - coords[t*3+2];
    float dist = sqrtf(dx*dx + dy*dy + dz*dz);
    const float coeff = -4.5f;  // -0.5 / (5/15)^2
    float* row = g_ea + (size_t)e * EDIM;
    #pragma unroll
    for (int g = 0; g < NGAUSS; g++) {
        float off = 5.0f * (float)g * (1.0f / 15.0f);
        float d0 = dist - off;
        row[g] = __expf(coeff * d0 * d0);
    }
    int kind = (isrec[s] != isrec[t]) ? 1 : 0;
    #pragma unroll
    for (int g = 0; g < NGAUSS; g++) row[NGAUSS + g] = sub[kind * NGAUSS + g];
}

// ---------------- fused per-layer edge MLP + scatter-add ----------------
extern __shared__ float smem[];

__global__ __launch_bounds__(LYR_THREADS, 1)
void k_layer(const int* __restrict__ ei,
             const float* __restrict__ W1, const float* __restrict__ b1,
             const float* __restrict__ W2, const float* __restrict__ b2) {
    float* sW1 = smem;                        // [160][128]
    float* sW2 = sW1 + CATD * HID;            // [128][64]
    float* sB1 = sW2 + HID * DIM;             // [128]
    float* sB2 = sB1 + HID;                   // [64]
    float* sX  = sB2 + DIM;                   // [64][XP]
    float* sH  = sX + TILE_E * XP;            // [64][HP]
    int*  sDst = (int*)(sH + TILE_E * HP);    // [64]

    const int tid = threadIdx.x;

    for (int i = tid; i < CATD * HID; i += LYR_THREADS) sW1[i] = W1[i];
    for (int i = tid; i < HID * DIM; i += LYR_THREADS)  sW2[i] = W2[i];
    if (tid < HID) sB1[tid] = b1[tid];
    if (tid < DIM) sB2[tid] = b2[tid];
    __syncthreads();

    const int* src = ei;
    const int* dst = ei + N_EDGES_C;
    const int tx = tid & 15;   // 16 col groups
    const int ty = tid >> 4;   // 16 row groups
    const int NT = N_EDGES_C / TILE_E;

    // bias pairs held in registers across tiles
    unsigned long long bias1[4], bias2[2];
    #pragma unroll
    for (int j = 0; j < 4; j++) PACK2(bias1[j], sB1[tx*8 + 2*j], sB1[tx*8 + 2*j + 1]);
    #pragma unroll
    for (int j = 0; j < 2; j++) PACK2(bias2[j], sB2[tx*4 + 2*j], sB2[tx*4 + 2*j + 1]);

    for (int tile = blockIdx.x; tile < NT; tile += gridDim.x) {
        const int e0 = tile * TILE_E;

        // ---- gather X rows: [h[dst] | h[src] | edge_attr], float4 granularity
        for (int t = tid; t < TILE_E * 40; t += LYR_THREADS) {
            int e = t / 40, q = t - e * 40;
            int ge = e0 + e;
            const float4* p;
            if (q < 16)        p = (const float4*)(g_h  + (size_t)dst[ge] * DIM) + q;
            else if (q < 32)   p = (const float4*)(g_h  + (size_t)src[ge] * DIM) + (q - 16);
            else               p = (const float4*)(g_ea + (size_t)ge * EDIM) + (q - 32);
            *(float4*)&sX[e * XP + q * 4] = *p;
        }
        if (tid < TILE_E) sDst[tid] = dst[e0 + tid];
        __syncthreads();

        // ---- GEMM1: [64,160] x [160,128], thread tile 4 rows x 8 cols, f32x2
        unsigned long long acc[4][4];
        #pragma unroll
        for (int i = 0; i < 4; i++)
            #pragma unroll
            for (int j = 0; j < 4; j++) acc[i][j] = bias1[j];

        const float* xrow = sX + (ty * 4) * XP;
        const float* wcol = sW1 + tx * 8;
        #pragma unroll 2
        for (int k = 0; k < CATD; k++) {
            unsigned long long a2[4];
            #pragma unroll
            for (int i = 0; i < 4; i++) {
                float a = xrow[i * XP + k];
                PACK2(a2[i], a, a);
            }
            ulonglong2 wA = *(const ulonglong2*)(wcol + k * HID);      // cols 0..3
            ulonglong2 wB = *(const ulonglong2*)(wcol + k * HID + 4);  // cols 4..7
            #pragma unroll
            for (int i = 0; i < 4; i++) {
                FFMA2(acc[i][0], a2[i], wA.x);
                FFMA2(acc[i][1], a2[i], wA.y);
                FFMA2(acc[i][2], a2[i], wB.x);
                FFMA2(acc[i][3], a2[i], wB.y);
            }
        }
        // silu -> sH
        #pragma unroll
        for (int i = 0; i < 4; i++) {
            float* hrow = sH + (ty * 4 + i) * HP + tx * 8;
            #pragma unroll
            for (int j = 0; j < 4; j++) {
                float v0, v1;
                UNPACK2(v0, v1, acc[i][j]);
                v0 = v0 / (1.0f + __expf(-v0));
                v1 = v1 / (1.0f + __expf(-v1));
                *(float2*)(hrow + 2*j) = make_float2(v0, v1);
            }
        }
        __syncthreads();

        // ---- GEMM2: [64,128] x [128,64], thread tile 4 rows x 4 cols, f32x2
        unsigned long long acc2[4][2];
        #pragma unroll
        for (int i = 0; i < 4; i++) {
            acc2[i][0] = bias2[0];
            acc2[i][1] = bias2[1];
        }
        const float* hrow = sH + (ty * 4) * HP;
        const float* w2col = sW2 + tx * 4;
        #pragma unroll 2
        for (int k = 0; k < HID; k++) {
            unsigned long long a2[4];
            #pragma unroll
            for (int i = 0; i < 4; i++) {
                float a = hrow[i * HP + k];
                PACK2(a2[i], a, a);
            }
            ulonglong2 w = *(const ulonglong2*)(w2col + k * DIM);  // 4 cols = 2 pairs
            #pragma unroll
            for (int i = 0; i < 4; i++) {
                FFMA2(acc2[i][0], a2[i], w.x);
                FFMA2(acc2[i][1], a2[i], w.y);
            }
        }
        #pragma unroll
        for (int i = 0; i < 4; i++) {
            int e = ty * 4 + i;
            float v0, v1, v2, v3;
            UNPACK2(v0, v1, acc2[i][0]);
            UNPACK2(v2, v3, acc2[i][1]);
            float* p = g_agg + (size_t)sDst[e] * DIM + tx * 4;
            red_add_v4(p, v0, v1, v2, v3);
        }
        __syncthreads();
    }
}

// ---------------- h = relu(h + agg); agg = 0 ----------------
__global__ void k_update() {
    int i = blockIdx.x * blockDim.x + threadIdx.x;
    if (i < N_NODES_C * DIM) {
        float v = g_h[i] + g_agg[i];
        g_h[i] = v > 0.0f ? v : 0.0f;
        g_agg[i] = 0.0f;
    }
}

// ---------------- pooling (segment sums + counts) ----------------
__global__ void k_pool(const int* __restrict__ batch) {
    int n = blockIdx.x * blockDim.x + threadIdx.x;
    if (n >= N_NODES_C) return;
    int b = batch[n];
    const float4* hp = (const float4*)(g_h + (size_t)n * DIM);
    float* pp = g_pool + b * DIM;
    #pragma unroll
    for (int q = 0; q < 16; q++) {
        float4 v = hp[q];
        red_add_v4(pp + q * 4, v.x, v.y, v.z, v.w);
    }
    atomicAdd(&g_cnt[b], 1.0f);
}

// ---------------- final FC ----------------
__global__ void k_final(const float* __restrict__ fcw, const float* __restrict__ fcb,
                        float* __restrict__ out) {
    int g = threadIdx.x;
    if (g < NGRAPHS) {
        float c = fmaxf(g_cnt[g], 1.0f);
        float inv = 1.0f / c;
        float s = 0.0f;
        #pragma unroll
        for (int d = 0; d < DIM; d++) s += (g_pool[g * DIM + d] * inv) * fcw[d];
        out[g] = s + fcb[0];
    }
}

extern "C" void kernel_launch(void* const* d_in, const int* in_sizes, int n_in,
                              void* d_out, int out_size) {
    const int*   atoms  = (const int*)d_in[0];
    const int*   ei     = (const int*)d_in[1];   // [2, E]: src row then dst row
    const float* coords = (const float*)d_in[2];
    const int*   isrec  = (const int*)d_in[3];
    const int*   batch  = (const int*)d_in[4];
    const float* emb    = (const float*)d_in[5];
    const float* sub    = (const float*)d_in[6];
    const float* W1     = (const float*)d_in[7]; // [4,160,128]
    const float* b1     = (const float*)d_in[8]; // [4,128]
    const float* W2     = (const float*)d_in[9]; // [4,128,64]
    const float* b2     = (const float*)d_in[10];// [4,64]
    const float* fcw    = (const float*)d_in[11];// [64,1]
    const float* fcb    = (const float*)d_in[12];// [1]
    float* out = (float*)d_out;

    cudaFuncSetAttribute(k_layer, cudaFuncAttributeMaxDynamicSharedMemorySize, SMEM_BYTES);

    k_init_nodes<<<(N_NODES_C * DIM + 255) / 256, 256>>>(atoms, emb);
    k_zero_pool<<<16, 256>>>();
    k_edge_attr<<<(N_EDGES_C + 255) / 256, 256>>>(ei, coords, isrec, sub);

    for (int l = 0; l < NLAYERS; l++) {
        k_layer<<<LYR_GRID, LYR_THREADS, SMEM_BYTES>>>(
            ei, W1 + (size_t)l * CATD * HID, b1 + (size_t)l * HID,
            W2 + (size_t)l * HID * DIM, b2 + (size_t)l * DIM);
        k_update<<<(N_NODES_C * DIM + 255) / 256, 256>>>();
    }

    k_pool<<<(N_NODES_C + 255) / 256, 256>>>(batch);
    k_final<<<1, 64>>>(fcw, fcb, out);
}